// round 6
// baseline (speedup 1.0000x reference)
#include <cuda_runtime.h>
#include <math.h>
#include <stdint.h>

// Problem constants
#define Bq 64
#define Tq 512
#define Iq 512
#define Hq 1024
#define Gq 4096      // 4*H
#define Cq 20
#define MTOT (Bq*Tq) // 32768
#define NBLK 128     // persistent blocks (<148 => all co-resident)

// lstm_layer shared-memory layout (floats)
#define WPAD 1028                 // 1024 + 4
#define HPAD 132                  // 128 + 4
#define HBUF (64*HPAD)            // one h chunk buffer: 8448 floats
#define WOFF 0                    // weights: 32 x WPAD = 32896
#define HOFF (32*WPAD)            // h double buffer: 2*HBUF = 16896
#define GOFF (HOFF + 2*HBUF)      // gate tile: 64 x 36 = 2304
#define SMEM_FLOATS (GOFF + 64*36)
#define SMEM_BYTES (SMEM_FLOATS * 4)

// ---- scratch (static device allocations; no cudaMalloc allowed) ----
__device__ float g_xproj[(size_t)MTOT * Gq];   // 512 MB, reused by both layers
__device__ float g_hseq1[(size_t)MTOT * Hq];   // 134 MB (T,B,H)
__device__ float g_hseq2[(size_t)MTOT * Hq];   // 134 MB (T,B,H)
__device__ float g_hbuf[2][Bq * Hq];           // h ping-pong
__device__ float g_emis[(size_t)MTOT * Cq];    // (T,B,C)
__device__ float g_llh[Bq];
__device__ unsigned g_cnt;
__device__ unsigned g_phase;

// ---- packed f32x2 helpers (FFMA2: 2x fp32 FMA per instruction) ----
__device__ __forceinline__ unsigned long long ffma2(unsigned long long a,
                                                    unsigned long long b,
                                                    unsigned long long c)
{
    unsigned long long d;
    asm("fma.rn.f32x2 %0, %1, %2, %3;" : "=l"(d) : "l"(a), "l"(b), "l"(c));
    return d;
}
__device__ __forceinline__ float u64lo(unsigned long long v)
{
    return __uint_as_float((unsigned)(v & 0xffffffffull));
}
__device__ __forceinline__ float u64hi(unsigned long long v)
{
    return __uint_as_float((unsigned)(v >> 32));
}

__device__ __forceinline__ void cp_async16(void* smem_dst, const void* gmem_src)
{
    uint32_t s = (uint32_t)__cvta_generic_to_shared(smem_dst);
    asm volatile("cp.async.cg.shared.global [%0], [%1], 16;\n" :: "r"(s), "l"(gmem_src));
}
__device__ __forceinline__ void cp_commit()
{
    asm volatile("cp.async.commit_group;\n");
}
__device__ __forceinline__ void cp_wait0()
{
    asm volatile("cp.async.wait_group 0;\n");
}

// ============================================================
// 128x64x(BK=16) fp32 SGEMM with FFMA2: Y = X(MxK)*W(NxK)^T + bias
// grid (N/64, M/128), 256 threads, 8m x 4n per thread.
// Tiles k-contiguous in smem ([row][16+4]), cp.async double-buffered.
// Thread n-cols: n = tx + 16*j  (bank-conflict-free W reads).
// If remap!=0, X row m = b*T+t and output row becomes t*B+b.
// ============================================================
__global__ void __launch_bounds__(256)
sgemm128(const float* __restrict__ X, const float* __restrict__ W,
         const float* __restrict__ bias, float* __restrict__ Y,
         int K, int remap)
{
    __shared__ float Xs[2][128][20];
    __shared__ float Ws[2][64][20];
    const int bn = blockIdx.x * 64;
    const int bm = blockIdx.y * 128;
    const int tid = threadIdx.x;
    const int ty = tid >> 4;      // 0..15 -> m0 = ty*8
    const int tx = tid & 15;      // n cols: tx + 16*j

    // tile-load coords
    const int xr = tid >> 2;               // also W row for W-load
    const int xk = (tid & 3) * 4;

    unsigned long long acc2[8][4] = {};

    // prefetch tile 0
    {
        #pragma unroll
        for (int l = 0; l < 2; l++) {
            int idx = tid + l * 256;
            int r = idx >> 2;
            int kk = (idx & 3) * 4;
            cp_async16(&Xs[0][r][kk], X + (size_t)(bm + r) * K + kk);
        }
        cp_async16(&Ws[0][xr][xk], W + (size_t)(bn + xr) * K + xk);
        cp_commit();
    }

    const int nb = K >> 4;
    for (int kb = 0; kb < nb; kb++) {
        const int buf = kb & 1;
        cp_wait0();
        __syncthreads();
        if (kb + 1 < nb) {
            int k0 = (kb + 1) << 4;
            #pragma unroll
            for (int l = 0; l < 2; l++) {
                int idx = tid + l * 256;
                int r = idx >> 2;
                int kk = (idx & 3) * 4;
                cp_async16(&Xs[buf ^ 1][r][kk], X + (size_t)(bm + r) * K + k0 + kk);
            }
            cp_async16(&Ws[buf ^ 1][xr][xk], W + (size_t)(bn + xr) * K + k0 + xk);
            cp_commit();
        }

        #pragma unroll
        for (int kk = 0; kk < 16; kk += 4) {
            ulonglong2 aq[8], wq[4];
            #pragma unroll
            for (int i = 0; i < 8; i++)
                aq[i] = *(const ulonglong2*)&Xs[buf][ty*8 + i][kk];
            #pragma unroll
            for (int j = 0; j < 4; j++)
                wq[j] = *(const ulonglong2*)&Ws[buf][tx + 16*j][kk];
            #pragma unroll
            for (int i = 0; i < 8; i++)
                #pragma unroll
                for (int j = 0; j < 4; j++) {
                    acc2[i][j] = ffma2(aq[i].x, wq[j].x, acc2[i][j]);
                    acc2[i][j] = ffma2(aq[i].y, wq[j].y, acc2[i][j]);
                }
        }
        // next iteration's top sync protects buf^1 overwrite
    }

    float bv[4];
    #pragma unroll
    for (int j = 0; j < 4; j++) bv[j] = bias[bn + tx + 16*j];
    #pragma unroll
    for (int i = 0; i < 8; i++) {
        int m = bm + ty*8 + i;
        int row = remap ? ((m & (Tq-1)) * Bq + (m >> 9)) : m;
        #pragma unroll
        for (int j = 0; j < 4; j++) {
            float v = u64lo(acc2[i][j]) + u64hi(acc2[i][j]) + bv[j];
            Y[(size_t)row * Gq + bn + tx + 16*j] = v;
        }
    }
}

// ============================================================
// Software grid barrier (all NBLK blocks resident by construction).
// ============================================================
__device__ __forceinline__ void gridbar(unsigned& myphase)
{
    __syncthreads();
    if (threadIdx.x == 0) {
        __threadfence();
        unsigned old = atomicAdd(&g_cnt, 1u);
        if (old == NBLK - 1) {
            g_cnt = 0;
            __threadfence();
            atomicAdd(&g_phase, 1u);
        } else {
            while (*(volatile unsigned*)&g_phase == myphase) { }
            __threadfence();
        }
    }
    __syncthreads();
    myphase++;
}

// ============================================================
// Persistent LSTM layer: 128 blocks x 256 threads, all T steps.
// Block owns 32 gate-cols (8 h-units x 4 gates).
// Whh slice (32x1024 = 128KB) lives in SMEM for the whole layer.
// h tile streamed per step in 128-k chunks, double-buffered cp.async.
// GEMM: thread tile 8b x 4n via FFMA2, 4-way k-split; smem reduction.
// c state in registers; h ping-pong in gmem + grid barrier per step.
// ============================================================
__global__ void __launch_bounds__(256, 1)
lstm_layer(const float* __restrict__ xproj, const float* __restrict__ Whh,
           const float* __restrict__ bhh, float* __restrict__ hseq)
{
    extern __shared__ float smem[];
    float* Wsm = smem + WOFF;   // [32][WPAD]
    float* Hsm = smem + HOFF;   // [2][64][HPAD]
    float* Gsm = smem + GOFF;   // [64][36]
    float* Rsm = smem + HOFF;   // reduction scratch (unions with Hsm)

    const int tid = threadIdx.x;
    const int bid = blockIdx.x;
    const int j0  = bid * 8;

    unsigned myphase = *(volatile unsigned*)&g_phase;

    // ---- preload weight slice into smem: rows c=0..31 -> (gate=c>>3, jl=c&7)
    #pragma unroll
    for (int l = 0; l < 32; l++) {
        int idx = tid + l * 256;          // 0..8191 float4 slots
        int c  = idx >> 8;                // 256 float4 per row
        int kq = idx & 255;
        int grow = (c >> 3) * Hq + j0 + (c & 7);
        float4 v = *(const float4*)(Whh + (size_t)grow * Hq + kq * 4);
        *(float4*)(Wsm + c * WPAD + kq * 4) = v;
    }

    // GEMM coords
    const int ks  = tid >> 6;     // 0..3 k-split
    const int pos = tid & 63;
    const int bq  = pos >> 3;     // b = bq + 8i
    const int nq  = pos & 7;      // n = nq + 8j

    // update coords (2 items per thread)
    float creg[2] = {0.0f, 0.0f};
    float bh[2][4];
    #pragma unroll
    for (int q = 0; q < 2; q++) {
        int p = tid + q * 256;
        int jl = p & 7;
        #pragma unroll
        for (int g2 = 0; g2 < 4; g2++) bh[q][g2] = bhh[g2 * Hq + j0 + jl];
    }

    // zero h buffer 0
    {
        int idx = bid * 512 + tid;
        g_hbuf[0][idx] = 0.0f;
        g_hbuf[0][idx + 256] = 0.0f;
    }
    gridbar(myphase);

    for (int t = 0; t < Tq; t++) {
        const float* hprev = g_hbuf[t & 1];
        float* hnext = g_hbuf[(t + 1) & 1];

        // prefetch chunk 0 into buf 0
        #pragma unroll
        for (int l = 0; l < 8; l++) {
            int idx = tid + l * 256;      // 2048 float4
            int row = idx >> 5;
            int kq  = idx & 31;
            cp_async16(Hsm + row * HPAD + kq * 4,
                       hprev + (size_t)row * Hq + kq * 4);
        }
        cp_commit();

        // prefetch this step's xproj gate values (hidden behind GEMM)
        float xg[2][4];
        #pragma unroll
        for (int q = 0; q < 2; q++) {
            int p = tid + q * 256;
            int b = p >> 3, jl = p & 7;
            size_t xb = ((size_t)t * Bq + b) * Gq + j0 + jl;
            #pragma unroll
            for (int g2 = 0; g2 < 4; g2++) xg[q][g2] = xproj[xb + (size_t)g2 * Hq];
        }

        unsigned long long acc2[8][4] = {};
        for (int kc = 0; kc < 8; kc++) {
            const int buf = kc & 1;
            cp_wait0();
            __syncthreads();
            if (kc < 7) {
                float* hdst = Hsm + (buf ^ 1) * HBUF;
                #pragma unroll
                for (int l = 0; l < 8; l++) {
                    int idx = tid + l * 256;
                    int row = idx >> 5;
                    int kq  = idx & 31;
                    cp_async16(hdst + row * HPAD + kq * 4,
                               hprev + (size_t)row * Hq + (kc + 1) * 128 + kq * 4);
                }
                cp_commit();
            }

            const float* hb = Hsm + buf * HBUF + ks * 32;
            const float* wb = Wsm + kc * 128 + ks * 32;
            #pragma unroll
            for (int kk = 0; kk < 32; kk += 4) {
                ulonglong2 hq[8];
                #pragma unroll
                for (int i = 0; i < 8; i++)
                    hq[i] = *(const ulonglong2*)(hb + (bq + 8*i) * HPAD + kk);
                ulonglong2 wq[4];
                #pragma unroll
                for (int j = 0; j < 4; j++)
                    wq[j] = *(const ulonglong2*)(wb + (nq + 8*j) * WPAD + kk);
                #pragma unroll
                for (int i = 0; i < 8; i++)
                    #pragma unroll
                    for (int j = 0; j < 4; j++) {
                        acc2[i][j] = ffma2(hq[i].x, wq[j].x, acc2[i][j]);
                        acc2[i][j] = ffma2(hq[i].y, wq[j].y, acc2[i][j]);
                    }
            }
        }
        __syncthreads();   // all compute done; Hsm free for reduction

        // unpack even/odd-k partial sums
        float acc[8][4];
        #pragma unroll
        for (int i = 0; i < 8; i++)
            #pragma unroll
            for (int j = 0; j < 4; j++)
                acc[i][j] = u64lo(acc2[i][j]) + u64hi(acc2[i][j]);

        // k-split reduction through smem
        if (ks > 0) {
            float* rp = Rsm + ((ks - 1) * 64 + pos) * 36;
            #pragma unroll
            for (int i = 0; i < 8; i++)
                *(float4*)(rp + i * 4) = *(float4*)acc[i];
        }
        __syncthreads();
        if (ks == 0) {
            #pragma unroll
            for (int s = 0; s < 3; s++) {
                const float* rp = Rsm + (s * 64 + pos) * 36;
                #pragma unroll
                for (int i = 0; i < 8; i++) {
                    float4 v = *(const float4*)(rp + i * 4);
                    acc[i][0] += v.x; acc[i][1] += v.y;
                    acc[i][2] += v.z; acc[i][3] += v.w;
                }
            }
            #pragma unroll
            for (int i = 0; i < 8; i++) {
                int b = bq + 8*i;
                #pragma unroll
                for (int j = 0; j < 4; j++)
                    Gsm[b * 36 + nq + 8*j] = acc[i][j];
            }
        }
        __syncthreads();

        // pointwise LSTM update
        #pragma unroll
        for (int q = 0; q < 2; q++) {
            int p = tid + q * 256;
            int b = p >> 3, jl = p & 7;
            float gi = Gsm[b*36 +      jl] + xg[q][0] + bh[q][0];
            float gf = Gsm[b*36 +  8 + jl] + xg[q][1] + bh[q][1];
            float gg = Gsm[b*36 + 16 + jl] + xg[q][2] + bh[q][2];
            float go = Gsm[b*36 + 24 + jl] + xg[q][3] + bh[q][3];
            float ig = 1.0f / (1.0f + expf(-gi));
            float fg = 1.0f / (1.0f + expf(-gf));
            float gv = tanhf(gg);
            float og = 1.0f / (1.0f + expf(-go));
            float cn = fg * creg[q] + ig * gv;
            creg[q] = cn;
            float hn = og * tanhf(cn);
            hnext[(size_t)b * Hq + j0 + jl] = hn;
            hseq[((size_t)t * Bq + b) * Hq + j0 + jl] = hn;
        }
        gridbar(myphase);
    }
}

// ============================================================
// Emissions: e[(t*B+b), c] = h2_row . fc_w[c] + fc_b[c]; one warp/row.
// ============================================================
__global__ void emis_kernel(const float* __restrict__ h2, const float* __restrict__ fcw,
                            const float* __restrict__ fcb, float* __restrict__ e)
{
    int warp = (blockIdx.x * blockDim.x + threadIdx.x) >> 5;
    int lane = threadIdx.x & 31;
    if (warp >= MTOT) return;
    const float* hr = h2 + (size_t)warp * Hq;
    float acc[Cq];
    #pragma unroll
    for (int cc = 0; cc < Cq; cc++) acc[cc] = 0.0f;
    for (int k = lane; k < Hq; k += 32) {
        float hv = hr[k];
        #pragma unroll
        for (int cc = 0; cc < Cq; cc++)
            acc[cc] = fmaf(hv, fcw[cc*Hq + k], acc[cc]);
    }
    #pragma unroll
    for (int cc = 0; cc < Cq; cc++) {
        float v = acc[cc];
        #pragma unroll
        for (int off = 16; off; off >>= 1) v += __shfl_down_sync(0xffffffffu, v, off);
        if (lane == 0) e[(size_t)warp * Cq + cc] = v + fcb[cc];
    }
}

// ============================================================
// CRF NLL per batch element. One warp per b. emissions in (T,B,C).
// ============================================================
__global__ void crf_kernel(const float* __restrict__ e, const int* __restrict__ labels,
                           const float* __restrict__ startt, const float* __restrict__ endt,
                           const float* __restrict__ trans, float* __restrict__ llh)
{
    int b = blockIdx.x;
    int lane = threadIdx.x;
    const int* lb = labels + (size_t)b * Tq;

    // ---- path score ----
    float part = 0.0f;
    int cnt = 0;
    for (int t = 1 + lane; t < Tq; t += 32) {
        int tag  = lb[t];
        int tagp = lb[t-1];
        if (tag != -1)
            part += trans[tagp*Cq + tag] + e[((size_t)t*Bq + b)*Cq + tag];
    }
    for (int t = lane; t < Tq; t += 32) cnt += (lb[t] != -1);
    #pragma unroll
    for (int off = 16; off; off >>= 1) {
        part += __shfl_down_sync(0xffffffffu, part, off);
        cnt  += __shfl_down_sync(0xffffffffu, cnt, off);
    }
    float score = 0.0f;
    if (lane == 0) {
        int tag0 = lb[0];
        score = startt[tag0] + e[(size_t)b*Cq + tag0] + part;
        int last = cnt - 1;
        score += endt[lb[last]];
    }

    // ---- logZ (forward algorithm) ----
    __shared__ float alpha[Cq];
    float tcol[Cq];
    if (lane < Cq) {
        #pragma unroll
        for (int cc = 0; cc < Cq; cc++) tcol[cc] = trans[cc*Cq + lane];
        alpha[lane] = startt[lane] + e[(size_t)b*Cq + lane];
    }
    __syncwarp();
    for (int t = 1; t < Tq; t++) {
        bool m = (lb[t] != -1);
        float av[Cq];
        #pragma unroll
        for (int cc = 0; cc < Cq; cc++) av[cc] = alpha[cc];
        float nxt = 0.0f;
        if (lane < Cq) {
            float mx = -1e30f;
            #pragma unroll
            for (int cc = 0; cc < Cq; cc++) mx = fmaxf(mx, av[cc] + tcol[cc]);
            float s = 0.0f;
            #pragma unroll
            for (int cc = 0; cc < Cq; cc++) s += expf(av[cc] + tcol[cc] - mx);
            nxt = mx + logf(s) + e[((size_t)t*Bq + b)*Cq + lane];
        }
        __syncwarp();
        if (m && lane < Cq) alpha[lane] = nxt;
        __syncwarp();
    }
    float v = (lane < Cq) ? alpha[lane] + endt[lane] : -1e30f;
    float mx = v;
    #pragma unroll
    for (int off = 16; off; off >>= 1) mx = fmaxf(mx, __shfl_xor_sync(0xffffffffu, mx, off));
    float sv = (lane < Cq) ? expf(v - mx) : 0.0f;
    #pragma unroll
    for (int off = 16; off; off >>= 1) sv += __shfl_xor_sync(0xffffffffu, sv, off);
    if (lane == 0) llh[b] = score - (mx + logf(sv));
}

__global__ void finalize_kernel(const float* __restrict__ llh, float* __restrict__ out)
{
    __shared__ float s[64];
    int lane = threadIdx.x;
    s[lane] = llh[lane];
    __syncthreads();
    #pragma unroll
    for (int off = 32; off; off >>= 1) {
        if (lane < off) s[lane] += s[lane + off];
        __syncthreads();
    }
    if (lane == 0) out[0] = -s[0] / (float)Bq;
}

// ============================================================
extern "C" void kernel_launch(void* const* d_in, const int* in_sizes, int n_in,
                              void* d_out, int out_size)
{
    const float* x     = (const float*)d_in[0];
    const int*   labels= (const int*)  d_in[1];
    // d_in[2] = lengths (unused; reference derives mask from labels)
    const float* Wih0  = (const float*)d_in[3];
    const float* Whh0  = (const float*)d_in[4];
    const float* bih0  = (const float*)d_in[5];
    const float* bhh0  = (const float*)d_in[6];
    const float* Wih1  = (const float*)d_in[7];
    const float* Whh1  = (const float*)d_in[8];
    const float* bih1  = (const float*)d_in[9];
    const float* bhh1  = (const float*)d_in[10];
    const float* fcw   = (const float*)d_in[11];
    const float* fcb   = (const float*)d_in[12];
    const float* startt= (const float*)d_in[13];
    const float* endt  = (const float*)d_in[14];
    const float* trans = (const float*)d_in[15];

    float *xproj, *hseq1, *hseq2, *emis, *llh;
    cudaGetSymbolAddress((void**)&xproj, g_xproj);
    cudaGetSymbolAddress((void**)&hseq1, g_hseq1);
    cudaGetSymbolAddress((void**)&hseq2, g_hseq2);
    cudaGetSymbolAddress((void**)&emis,  g_emis);
    cudaGetSymbolAddress((void**)&llh,   g_llh);

    cudaFuncSetAttribute(lstm_layer, cudaFuncAttributeMaxDynamicSharedMemorySize, SMEM_BYTES);

    dim3 gsX(Gq/64, MTOT/128);       // (64, 256)

    // ---- layer 1 ----
    sgemm128<<<gsX, 256>>>(x, Wih0, bih0, xproj, Iq, /*remap=*/1);
    lstm_layer<<<NBLK, 256, SMEM_BYTES>>>(xproj, Whh0, bhh0, hseq1);

    // ---- layer 2 ----
    sgemm128<<<gsX, 256>>>(hseq1, Wih1, bih1, xproj, Hq, /*remap=*/0);
    lstm_layer<<<NBLK, 256, SMEM_BYTES>>>(xproj, Whh1, bhh1, hseq2);

    // ---- emissions + CRF ----
    emis_kernel<<<(MTOT*32)/256, 256>>>(hseq2, fcw, fcb, emis);
    crf_kernel<<<Bq, 32>>>(emis, labels, startt, endt, trans, llh);
    finalize_kernel<<<1, 64>>>(llh, (float*)d_out);
}